// round 1
// baseline (speedup 1.0000x reference)
#include <cuda_runtime.h>
#include <math.h>

// Problem constants
#define BATCH 32
#define NTOK  784
#define DIM   512
#define NH    8
#define HD    64
#define HH    28
#define WW    28
#define DA    49

// -------- scratch (__device__ globals; no allocations allowed) --------
__device__ float g_q    [BATCH * NTOK * DIM];       // 51.4 MB
__device__ float g_kv   [BATCH * NTOK * 2 * DIM];   // 102.8 MB  (k at +0, v at +512 within 1024-stride row)
__device__ float g_agent[BATCH * DA * DIM];         // 3.2 MB
__device__ float g_agent_v[BATCH * NH * DA * HD];   // 3.2 MB
__device__ float g_pos_bias[NH * DA * NTOK];        // [h,a,n]
__device__ float g_agent_bias[NH * NTOK * DA];      // [h,n,a]
__device__ float g_attn [BATCH * NTOK * DIM];       // 51.4 MB (attn out + dwc, pre-proj)

// ======================= SGEMM: C[M,N] = A[M,K] * W[N,K]^T (+bias) ======================
// BM=BN=128, BK=8, 256 threads, 8x8 microtile split as (4 + 4 offset 64) for
// conflict-free LDS.128 reads.
__device__ __forceinline__ void sgemm_body(const float* __restrict__ A,
                                           const float* __restrict__ W,
                                           float* __restrict__ C,
                                           const float* __restrict__ bias,
                                           int K, int ldc)
{
    __shared__ float As[8][128];
    __shared__ float Bs[8][128];
    const int row0 = blockIdx.y * 128;
    const int col0 = blockIdx.x * 128;
    const int tid = threadIdx.x;
    const int tx = tid & 15, ty = tid >> 4;
    const int l_row = tid >> 1;
    const int l_kc  = (tid & 1) * 4;

    const float* Ap = A + (size_t)(row0 + l_row) * K + l_kc;
    const float* Wp = W + (size_t)(col0 + l_row) * K + l_kc;

    float acc[8][8];
#pragma unroll
    for (int i = 0; i < 8; i++)
#pragma unroll
        for (int j = 0; j < 8; j++) acc[i][j] = 0.f;

    for (int k0 = 0; k0 < K; k0 += 8) {
        float4 av = *(const float4*)(Ap + k0);
        float4 wv = *(const float4*)(Wp + k0);
        As[l_kc + 0][l_row] = av.x; As[l_kc + 1][l_row] = av.y;
        As[l_kc + 2][l_row] = av.z; As[l_kc + 3][l_row] = av.w;
        Bs[l_kc + 0][l_row] = wv.x; Bs[l_kc + 1][l_row] = wv.y;
        Bs[l_kc + 2][l_row] = wv.z; Bs[l_kc + 3][l_row] = wv.w;
        __syncthreads();
#pragma unroll
        for (int kk = 0; kk < 8; kk++) {
            float4 a0 = *(const float4*)&As[kk][ty * 4];
            float4 a1 = *(const float4*)&As[kk][64 + ty * 4];
            float4 b0 = *(const float4*)&Bs[kk][tx * 4];
            float4 b1 = *(const float4*)&Bs[kk][64 + tx * 4];
            float ar[8] = {a0.x, a0.y, a0.z, a0.w, a1.x, a1.y, a1.z, a1.w};
            float br[8] = {b0.x, b0.y, b0.z, b0.w, b1.x, b1.y, b1.z, b1.w};
#pragma unroll
            for (int i = 0; i < 8; i++)
#pragma unroll
                for (int j = 0; j < 8; j++)
                    acc[i][j] = fmaf(ar[i], br[j], acc[i][j]);
        }
        __syncthreads();
    }

#pragma unroll
    for (int i = 0; i < 8; i++) {
        int r = row0 + ((i < 4) ? (ty * 4 + i) : (64 + ty * 4 + i - 4));
#pragma unroll
        for (int jh = 0; jh < 2; jh++) {
            int c = col0 + ((jh == 0) ? (tx * 4) : (64 + tx * 4));
            float4 o;
            o.x = acc[i][jh * 4 + 0]; o.y = acc[i][jh * 4 + 1];
            o.z = acc[i][jh * 4 + 2]; o.w = acc[i][jh * 4 + 3];
            if (bias) { o.x += bias[c]; o.y += bias[c + 1]; o.z += bias[c + 2]; o.w += bias[c + 3]; }
            *(float4*)&C[(size_t)r * ldc + c] = o;
        }
    }
}

__global__ void gemm_q(const float* __restrict__ x, const float* __restrict__ w) {
    sgemm_body(x, w, g_q, nullptr, DIM, DIM);
}
__global__ void gemm_kv(const float* __restrict__ x, const float* __restrict__ w) {
    sgemm_body(x, w, g_kv, nullptr, DIM, 2 * DIM);
}
__global__ void gemm_proj(const float* __restrict__ w, const float* __restrict__ b,
                          float* __restrict__ out) {
    sgemm_body(g_attn, w, out, b, DIM, DIM);
}

// ======================= agent = 4x4 avg pool of q image =======================
__global__ void pool_agent()
{
    int ba = blockIdx.x;              // b*49 + a
    int b = ba / DA, a = ba % DA;
    int ai = a / 7, aj = a % 7;
    int c = threadIdx.x;              // 512
    float s = 0.f;
#pragma unroll
    for (int di = 0; di < 4; di++)
#pragma unroll
        for (int dj = 0; dj < 4; dj++)
            s += g_q[((size_t)(b * NTOK + (ai * 4 + di) * WW + (aj * 4 + dj))) * DIM + c];
    g_agent[(size_t)ba * DIM + c] = s * 0.0625f;
}

// ======================= bias precompute =======================
// jax.image.resize(bilinear, antialias=False) 7->28: sample s=(i+0.5)/4-0.5,
// triangle weights; edge renormalization == index clamping for this geometry.
__device__ __forceinline__ float bilin7(const float* __restrict__ t, int i, int j)
{
    float si = (i - 1.5f) * 0.25f;
    float sj = (j - 1.5f) * 0.25f;
    float fi = floorf(si), fj = floorf(sj);
    int i0 = (int)fi, j0 = (int)fj;
    float wi = si - fi, wj = sj - fj;
    int i0c = max(0, min(6, i0)), i1c = max(0, min(6, i0 + 1));
    int j0c = max(0, min(6, j0)), j1c = max(0, min(6, j0 + 1));
    float v00 = t[i0c * 7 + j0c], v01 = t[i0c * 7 + j1c];
    float v10 = t[i1c * 7 + j0c], v11 = t[i1c * 7 + j1c];
    return (1.f - wi) * ((1.f - wj) * v00 + wj * v01)
         +        wi  * ((1.f - wj) * v10 + wj * v11);
}

__global__ void build_bias(const float* __restrict__ an_bias, const float* __restrict__ na_bias,
                           const float* __restrict__ ah_bias, const float* __restrict__ aw_bias,
                           const float* __restrict__ ha_bias, const float* __restrict__ wa_bias)
{
    int ha = blockIdx.x;              // h*49 + a
    int h = ha / DA, a = ha % DA;
    int n = threadIdx.x;              // 784
    int i = n / WW, j = n % WW;
    // pos_bias[h,a,n] = bilin(an_bias[h,a])[i,j] + ah_bias[h,a,i] + aw_bias[h,a,j]
    g_pos_bias[(size_t)ha * NTOK + n] =
        bilin7(an_bias + (size_t)ha * 49, i, j) + ah_bias[ha * HH + i] + aw_bias[ha * WW + j];
    // agent_bias[h,n,a] = bilin(na_bias[h,a])[i,j] + ha_bias[h,i,a] + wa_bias[h,j,a]
    g_agent_bias[((size_t)h * NTOK + n) * DA + a] =
        bilin7(na_bias + (size_t)ha * 49, i, j)
        + ha_bias[(h * HH + i) * DA + a] + wa_bias[(h * WW + j) * DA + a];
}

// ======================= agent attention: softmax_n(ah*s . k + pos) @ v =======================
// one block per (b,h,a), 256 threads
__global__ void agent_attn()
{
    int a = blockIdx.x, h = blockIdx.y, b = blockIdx.z;
    __shared__ float sA[HD];
    __shared__ float sS[NTOK];
    __shared__ float red[256];
    int tid = threadIdx.x;

    if (tid < HD)
        sA[tid] = g_agent[((size_t)(b * DA + a)) * DIM + h * HD + tid] * 0.125f;
    __syncthreads();

    const float* pb = g_pos_bias + (size_t)(h * DA + a) * NTOK;
    for (int n = tid; n < NTOK; n += 256) {
        const float4* kr = (const float4*)(g_kv + ((size_t)(b * NTOK + n)) * (2 * DIM) + h * HD);
        float s = 0.f;
#pragma unroll
        for (int d4 = 0; d4 < 16; d4++) {
            float4 k4 = kr[d4];
            s = fmaf(sA[d4 * 4 + 0], k4.x, s);
            s = fmaf(sA[d4 * 4 + 1], k4.y, s);
            s = fmaf(sA[d4 * 4 + 2], k4.z, s);
            s = fmaf(sA[d4 * 4 + 3], k4.w, s);
        }
        sS[n] = s + pb[n];
    }
    __syncthreads();

    // max
    float lm = -1e30f;
    for (int n = tid; n < NTOK; n += 256) lm = fmaxf(lm, sS[n]);
    red[tid] = lm; __syncthreads();
    for (int s = 128; s > 0; s >>= 1) {
        if (tid < s) red[tid] = fmaxf(red[tid], red[tid + s]);
        __syncthreads();
    }
    float m = red[0];
    __syncthreads();

    // exp + sum
    float ls = 0.f;
    for (int n = tid; n < NTOK; n += 256) { float e = __expf(sS[n] - m); sS[n] = e; ls += e; }
    red[tid] = ls; __syncthreads();
    for (int s = 128; s > 0; s >>= 1) {
        if (tid < s) red[tid] += red[tid + s];
        __syncthreads();
    }
    float inv = 1.f / red[0];
    __syncthreads();

    // agent_v[a,d] = sum_n p[n] * v[n,d]
    int d = tid & 63, ch = tid >> 6;          // 64 d's x 4 chunks of 196
    float acc = 0.f;
    const float* vb = g_kv + DIM + h * HD + d;
    int n0 = ch * 196;
    for (int n = n0; n < n0 + 196; n++)
        acc = fmaf(sS[n], vb[((size_t)(b * NTOK + n)) * (2 * DIM)], acc);
    red[tid] = acc; __syncthreads();
    if (tid < 64) {
        float r = (red[tid] + red[tid + 64] + red[tid + 128] + red[tid + 192]) * inv;
        g_agent_v[(((size_t)(b * NH + h)) * DA + a) * HD + tid] = r;
    }
}

// ======================= q attention: softmax_a(q*s . ah + agent_bias) @ agent_v =======================
// one block per (b,h), 256 threads, each thread owns whole tokens
__global__ void q_attn()
{
    int h = blockIdx.x, b = blockIdx.y;
    __shared__ float sA [DA * HD];
    __shared__ float sAV[DA * HD];
    int tid = threadIdx.x;
    for (int i = tid; i < DA * HD; i += 256) {
        int a = i >> 6, d = i & 63;
        sA [i] = g_agent[((size_t)(b * DA + a)) * DIM + h * HD + d];
        sAV[i] = g_agent_v[(((size_t)(b * NH + h)) * DA + a) * HD + d];
    }
    __syncthreads();

    for (int n = tid; n < NTOK; n += 256) {
        float qr[HD];
        const float4* qp = (const float4*)(g_q + ((size_t)(b * NTOK + n)) * DIM + h * HD);
#pragma unroll
        for (int d4 = 0; d4 < 16; d4++) {
            float4 v4 = qp[d4];
            qr[d4 * 4 + 0] = v4.x * 0.125f; qr[d4 * 4 + 1] = v4.y * 0.125f;
            qr[d4 * 4 + 2] = v4.z * 0.125f; qr[d4 * 4 + 3] = v4.w * 0.125f;
        }
        const float* ab = g_agent_bias + ((size_t)(h * NTOK + n)) * DA;
        float sc[DA];
        float m = -1e30f;
        for (int a = 0; a < DA; a++) {
            float s = ab[a];
            const float* Ar = &sA[a * HD];
#pragma unroll
            for (int d = 0; d < HD; d++) s = fmaf(qr[d], Ar[d], s);
            sc[a] = s; m = fmaxf(m, s);
        }
        float sum = 0.f;
        for (int a = 0; a < DA; a++) { float e = __expf(sc[a] - m); sc[a] = e; sum += e; }
        float inv = 1.f / sum;

        float o[HD];
#pragma unroll
        for (int d = 0; d < HD; d++) o[d] = 0.f;
        for (int a = 0; a < DA; a++) {
            float p = sc[a] * inv;
            const float* Vr = &sAV[a * HD];
#pragma unroll
            for (int d = 0; d < HD; d++) o[d] = fmaf(p, Vr[d], o[d]);
        }
        float* op = g_attn + ((size_t)(b * NTOK + n)) * DIM + h * HD;
#pragma unroll
        for (int d4 = 0; d4 < 16; d4++) {
            float4 v4;
            v4.x = o[d4 * 4 + 0]; v4.y = o[d4 * 4 + 1];
            v4.z = o[d4 * 4 + 2]; v4.w = o[d4 * 4 + 3];
            ((float4*)op)[d4] = v4;
        }
    }
}

// ======================= depthwise 3x3 conv on v, added into g_attn =======================
__global__ void dwc_add(const float* __restrict__ w, const float* __restrict__ bias)
{
    int n = blockIdx.x, b = blockIdx.y;
    int c = threadIdx.x;              // 512
    int i = n / WW, j = n % WW;
    float acc = bias[c];
#pragma unroll
    for (int di = 0; di < 3; di++) {
        int ii = i + di - 1;
        if (ii < 0 || ii > HH - 1) continue;
#pragma unroll
        for (int dj = 0; dj < 3; dj++) {
            int jj = j + dj - 1;
            if (jj < 0 || jj > WW - 1) continue;
            acc = fmaf(w[c * 9 + di * 3 + dj],
                       g_kv[((size_t)(b * NTOK + ii * WW + jj)) * (2 * DIM) + DIM + c], acc);
        }
    }
    g_attn[((size_t)(b * NTOK + n)) * DIM + c] += acc;
}

// ======================= launch =======================
extern "C" void kernel_launch(void* const* d_in, const int* in_sizes, int n_in,
                              void* d_out, int out_size)
{
    const float* x       = (const float*)d_in[0];
    const float* q_w     = (const float*)d_in[1];
    const float* kv_w    = (const float*)d_in[2];
    const float* proj_w  = (const float*)d_in[3];
    const float* proj_b  = (const float*)d_in[4];
    const float* dwc_w   = (const float*)d_in[5];
    const float* dwc_b   = (const float*)d_in[6];
    const float* an_bias = (const float*)d_in[7];
    const float* na_bias = (const float*)d_in[8];
    const float* ah_bias = (const float*)d_in[9];
    const float* aw_bias = (const float*)d_in[10];
    const float* ha_bias = (const float*)d_in[11];
    const float* wa_bias = (const float*)d_in[12];
    float* out = (float*)d_out;

    gemm_q <<<dim3(DIM / 128, (BATCH * NTOK) / 128), 256>>>(x, q_w);
    gemm_kv<<<dim3((2 * DIM) / 128, (BATCH * NTOK) / 128), 256>>>(x, kv_w);
    pool_agent<<<BATCH * DA, DIM>>>();
    build_bias<<<NH * DA, NTOK>>>(an_bias, na_bias, ah_bias, aw_bias, ha_bias, wa_bias);
    agent_attn<<<dim3(DA, NH, BATCH), 256>>>();
    q_attn<<<dim3(NH, BATCH), 256>>>();
    dwc_add<<<dim3(NTOK, BATCH), DIM>>>(dwc_w, dwc_b);
    gemm_proj<<<dim3(DIM / 128, (BATCH * NTOK) / 128), 256>>>(proj_w, proj_b, out);
}

// round 2
// speedup vs baseline: 1.4852x; 1.4852x over previous
#include <cuda_runtime.h>
#include <math.h>
#include <stdint.h>

// Problem constants
#define BATCH 32
#define NTOK  784
#define DIM   512
#define NH    8
#define HD    64
#define HH    28
#define WW    28
#define DA    49

// -------- scratch (__device__ globals; no allocations allowed) --------
__device__ float g_q    [BATCH * NTOK * DIM];
__device__ float g_kv   [BATCH * NTOK * 2 * DIM];   // k at +0, v at +512 within 1024-stride row
__device__ float g_agent[BATCH * DA * DIM];
__device__ float g_agent_v[BATCH * NH * DA * HD];
__device__ float g_pos_bias[NH * DA * NTOK];        // [h,a,n]
__device__ float g_agent_bias[NH * NTOK * DA];      // [h,n,a]
__device__ float g_attn [BATCH * NTOK * DIM];

// ======================= TF32 tensor-core GEMM =======================
// C[M,N] = A[M,K] @ W[N,K]^T (+bias).  BM=BN=128, BK=16, 256 thr = 8 warps (2x4),
// warp tile 64x32 = 4x4 of mma.m16n8k8.  Smem padded [128][20] -> conflict-free frags.

__device__ __forceinline__ uint32_t f2tf(float f) {
    uint32_t u;
    asm("cvt.rna.tf32.f32 %0, %1;" : "=r"(u) : "f"(f));
    return u;
}

__device__ __forceinline__ void mma_tf32(float* d, const uint32_t* a, const uint32_t* b) {
    asm volatile(
        "mma.sync.aligned.m16n8k8.row.col.f32.tf32.tf32.f32 "
        "{%0,%1,%2,%3}, {%4,%5,%6,%7}, {%8,%9}, {%0,%1,%2,%3};"
        : "+f"(d[0]), "+f"(d[1]), "+f"(d[2]), "+f"(d[3])
        : "r"(a[0]), "r"(a[1]), "r"(a[2]), "r"(a[3]), "r"(b[0]), "r"(b[1]));
}

__device__ __forceinline__ void tf32_gemm_body(const float* __restrict__ A,
                                               const float* __restrict__ W,
                                               float* __restrict__ C,
                                               const float* __restrict__ bias,
                                               int K, int ldc)
{
    __shared__ uint32_t As[128][20];
    __shared__ uint32_t Bs[128][20];
    const int row0 = blockIdx.y * 128;
    const int col0 = blockIdx.x * 128;
    const int tid  = threadIdx.x;
    const int lane = tid & 31;
    const int warp = tid >> 5;
    const int wm = warp >> 2;            // 0..1 -> 64-row slab
    const int wn = warp & 3;             // 0..3 -> 32-col slab
    const int gid = lane >> 2;           // group id 0..7
    const int tig = lane & 3;            // thread-in-group

    const int lr = tid >> 1;             // 0..127 (tile row for loads)
    const int lc = (tid & 1) * 8;        // 0 or 8

    const float* Ap = A + (size_t)(row0 + lr) * K + lc;
    const float* Wp = W + (size_t)(col0 + lr) * K + lc;

    float acc[4][4][4];
#pragma unroll
    for (int i = 0; i < 4; i++)
#pragma unroll
        for (int j = 0; j < 4; j++)
#pragma unroll
            for (int r = 0; r < 4; r++) acc[i][j][r] = 0.f;

    float4 av0 = *(const float4*)(Ap);
    float4 av1 = *(const float4*)(Ap + 4);
    float4 wv0 = *(const float4*)(Wp);
    float4 wv1 = *(const float4*)(Wp + 4);

    for (int k0 = 0; k0 < K; k0 += 16) {
        As[lr][lc + 0] = f2tf(av0.x); As[lr][lc + 1] = f2tf(av0.y);
        As[lr][lc + 2] = f2tf(av0.z); As[lr][lc + 3] = f2tf(av0.w);
        As[lr][lc + 4] = f2tf(av1.x); As[lr][lc + 5] = f2tf(av1.y);
        As[lr][lc + 6] = f2tf(av1.z); As[lr][lc + 7] = f2tf(av1.w);
        Bs[lr][lc + 0] = f2tf(wv0.x); Bs[lr][lc + 1] = f2tf(wv0.y);
        Bs[lr][lc + 2] = f2tf(wv0.z); Bs[lr][lc + 3] = f2tf(wv0.w);
        Bs[lr][lc + 4] = f2tf(wv1.x); Bs[lr][lc + 5] = f2tf(wv1.y);
        Bs[lr][lc + 6] = f2tf(wv1.z); Bs[lr][lc + 7] = f2tf(wv1.w);
        __syncthreads();

        if (k0 + 16 < K) {                      // prefetch next slab over the MMA block
            av0 = *(const float4*)(Ap + k0 + 16);
            av1 = *(const float4*)(Ap + k0 + 20);
            wv0 = *(const float4*)(Wp + k0 + 16);
            wv1 = *(const float4*)(Wp + k0 + 20);
        }

#pragma unroll
        for (int kk = 0; kk < 16; kk += 8) {
            uint32_t af[4][4], bf[4][2];
#pragma unroll
            for (int mt = 0; mt < 4; mt++) {
                int r = wm * 64 + mt * 16 + gid;
                af[mt][0] = As[r][kk + tig];
                af[mt][1] = As[r + 8][kk + tig];
                af[mt][2] = As[r][kk + tig + 4];
                af[mt][3] = As[r + 8][kk + tig + 4];
            }
#pragma unroll
            for (int nt = 0; nt < 4; nt++) {
                int cb = wn * 32 + nt * 8 + gid;
                bf[nt][0] = Bs[cb][kk + tig];
                bf[nt][1] = Bs[cb][kk + tig + 4];
            }
#pragma unroll
            for (int mt = 0; mt < 4; mt++)
#pragma unroll
                for (int nt = 0; nt < 4; nt++)
                    mma_tf32(acc[mt][nt], af[mt], bf[nt]);
        }
        __syncthreads();
    }

    // epilogue: C fragment c0,c1 at (row=gid, col=2*tig..+1), c2,c3 at row+8
#pragma unroll
    for (int mt = 0; mt < 4; mt++) {
        int r = row0 + wm * 64 + mt * 16 + gid;
#pragma unroll
        for (int nt = 0; nt < 4; nt++) {
            int c = col0 + wn * 32 + nt * 8 + 2 * tig;
            float2 v0 = make_float2(acc[mt][nt][0], acc[mt][nt][1]);
            float2 v1 = make_float2(acc[mt][nt][2], acc[mt][nt][3]);
            if (bias) {
                float2 bb = *(const float2*)&bias[c];
                v0.x += bb.x; v0.y += bb.y;
                v1.x += bb.x; v1.y += bb.y;
            }
            *(float2*)&C[(size_t)r * ldc + c]       = v0;
            *(float2*)&C[(size_t)(r + 8) * ldc + c] = v1;
        }
    }
}

__global__ void gemm_q(const float* __restrict__ x, const float* __restrict__ w) {
    tf32_gemm_body(x, w, g_q, nullptr, DIM, DIM);
}
__global__ void gemm_kv(const float* __restrict__ x, const float* __restrict__ w) {
    tf32_gemm_body(x, w, g_kv, nullptr, DIM, 2 * DIM);
}
__global__ void gemm_proj(const float* __restrict__ w, const float* __restrict__ b,
                          float* __restrict__ out) {
    tf32_gemm_body(g_attn, w, out, b, DIM, DIM);
}

// ======================= agent = 4x4 avg pool of q image =======================
__global__ void pool_agent()
{
    int ba = blockIdx.x;              // b*49 + a
    int b = ba / DA, a = ba % DA;
    int ai = a / 7, aj = a % 7;
    int c = threadIdx.x;              // 512
    float s = 0.f;
#pragma unroll
    for (int di = 0; di < 4; di++)
#pragma unroll
        for (int dj = 0; dj < 4; dj++)
            s += g_q[((size_t)(b * NTOK + (ai * 4 + di) * WW + (aj * 4 + dj))) * DIM + c];
    g_agent[(size_t)ba * DIM + c] = s * 0.0625f;
}

// ======================= bias precompute =======================
__device__ __forceinline__ float bilin7(const float* __restrict__ t, int i, int j)
{
    float si = (i - 1.5f) * 0.25f;
    float sj = (j - 1.5f) * 0.25f;
    float fi = floorf(si), fj = floorf(sj);
    int i0 = (int)fi, j0 = (int)fj;
    float wi = si - fi, wj = sj - fj;
    int i0c = max(0, min(6, i0)), i1c = max(0, min(6, i0 + 1));
    int j0c = max(0, min(6, j0)), j1c = max(0, min(6, j0 + 1));
    float v00 = t[i0c * 7 + j0c], v01 = t[i0c * 7 + j1c];
    float v10 = t[i1c * 7 + j0c], v11 = t[i1c * 7 + j1c];
    return (1.f - wi) * ((1.f - wj) * v00 + wj * v01)
         +        wi  * ((1.f - wj) * v10 + wj * v11);
}

__global__ void build_bias(const float* __restrict__ an_bias, const float* __restrict__ na_bias,
                           const float* __restrict__ ah_bias, const float* __restrict__ aw_bias,
                           const float* __restrict__ ha_bias, const float* __restrict__ wa_bias)
{
    int ha = blockIdx.x;              // h*49 + a
    int h = ha / DA, a = ha % DA;
    int n = threadIdx.x;              // 784
    int i = n / WW, j = n % WW;
    g_pos_bias[(size_t)ha * NTOK + n] =
        bilin7(an_bias + (size_t)ha * 49, i, j) + ah_bias[ha * HH + i] + aw_bias[ha * WW + j];
    g_agent_bias[((size_t)h * NTOK + n) * DA + a] =
        bilin7(na_bias + (size_t)ha * 49, i, j)
        + ha_bias[(h * HH + i) * DA + a] + wa_bias[(h * WW + j) * DA + a];
}

// ======================= agent attention =======================
__global__ void agent_attn()
{
    int a = blockIdx.x, h = blockIdx.y, b = blockIdx.z;
    __shared__ float sA[HD];
    __shared__ float sS[NTOK];
    __shared__ float red[256];
    int tid = threadIdx.x;

    if (tid < HD)
        sA[tid] = g_agent[((size_t)(b * DA + a)) * DIM + h * HD + tid] * 0.125f;
    __syncthreads();

    const float* pb = g_pos_bias + (size_t)(h * DA + a) * NTOK;
    for (int n = tid; n < NTOK; n += 256) {
        const float4* kr = (const float4*)(g_kv + ((size_t)(b * NTOK + n)) * (2 * DIM) + h * HD);
        float s = 0.f;
#pragma unroll
        for (int d4 = 0; d4 < 16; d4++) {
            float4 k4 = kr[d4];
            s = fmaf(sA[d4 * 4 + 0], k4.x, s);
            s = fmaf(sA[d4 * 4 + 1], k4.y, s);
            s = fmaf(sA[d4 * 4 + 2], k4.z, s);
            s = fmaf(sA[d4 * 4 + 3], k4.w, s);
        }
        sS[n] = s + pb[n];
    }
    __syncthreads();

    float lm = -1e30f;
    for (int n = tid; n < NTOK; n += 256) lm = fmaxf(lm, sS[n]);
    red[tid] = lm; __syncthreads();
    for (int s = 128; s > 0; s >>= 1) {
        if (tid < s) red[tid] = fmaxf(red[tid], red[tid + s]);
        __syncthreads();
    }
    float m = red[0];
    __syncthreads();

    float ls = 0.f;
    for (int n = tid; n < NTOK; n += 256) { float e = __expf(sS[n] - m); sS[n] = e; ls += e; }
    red[tid] = ls; __syncthreads();
    for (int s = 128; s > 0; s >>= 1) {
        if (tid < s) red[tid] += red[tid + s];
        __syncthreads();
    }
    float inv = 1.f / red[0];
    __syncthreads();

    int d = tid & 63, ch = tid >> 6;
    float acc = 0.f;
    const float* vb = g_kv + DIM + h * HD + d;
    int n0 = ch * 196;
    for (int n = n0; n < n0 + 196; n++)
        acc = fmaf(sS[n], vb[((size_t)(b * NTOK + n)) * (2 * DIM)], acc);
    red[tid] = acc; __syncthreads();
    if (tid < 64) {
        float r = (red[tid] + red[tid + 64] + red[tid + 128] + red[tid + 192]) * inv;
        g_agent_v[(((size_t)(b * NH + h)) * DA + a) * HD + tid] = r;
    }
}

// ======================= q attention =======================
__global__ void q_attn()
{
    int h = blockIdx.x, b = blockIdx.y;
    __shared__ float sA [DA * HD];
    __shared__ float sAV[DA * HD];
    int tid = threadIdx.x;
    for (int i = tid; i < DA * HD; i += 256) {
        int a = i >> 6, d = i & 63;
        sA [i] = g_agent[((size_t)(b * DA + a)) * DIM + h * HD + d];
        sAV[i] = g_agent_v[(((size_t)(b * NH + h)) * DA + a) * HD + d];
    }
    __syncthreads();

    for (int n = tid; n < NTOK; n += 256) {
        float qr[HD];
        const float4* qp = (const float4*)(g_q + ((size_t)(b * NTOK + n)) * DIM + h * HD);
#pragma unroll
        for (int d4 = 0; d4 < 16; d4++) {
            float4 v4 = qp[d4];
            qr[d4 * 4 + 0] = v4.x * 0.125f; qr[d4 * 4 + 1] = v4.y * 0.125f;
            qr[d4 * 4 + 2] = v4.z * 0.125f; qr[d4 * 4 + 3] = v4.w * 0.125f;
        }
        const float* ab = g_agent_bias + ((size_t)(h * NTOK + n)) * DA;
        float sc[DA];
        float m = -1e30f;
        for (int a = 0; a < DA; a++) {
            float s = ab[a];
            const float* Ar = &sA[a * HD];
#pragma unroll
            for (int d = 0; d < HD; d++) s = fmaf(qr[d], Ar[d], s);
            sc[a] = s; m = fmaxf(m, s);
        }
        float sum = 0.f;
        for (int a = 0; a < DA; a++) { float e = __expf(sc[a] - m); sc[a] = e; sum += e; }
        float inv = 1.f / sum;

        float o[HD];
#pragma unroll
        for (int d = 0; d < HD; d++) o[d] = 0.f;
        for (int a = 0; a < DA; a++) {
            float p = sc[a] * inv;
            const float* Vr = &sAV[a * HD];
#pragma unroll
            for (int d = 0; d < HD; d++) o[d] = fmaf(p, Vr[d], o[d]);
        }
        float* op = g_attn + ((size_t)(b * NTOK + n)) * DIM + h * HD;
#pragma unroll
        for (int d4 = 0; d4 < 16; d4++) {
            float4 v4;
            v4.x = o[d4 * 4 + 0]; v4.y = o[d4 * 4 + 1];
            v4.z = o[d4 * 4 + 2]; v4.w = o[d4 * 4 + 3];
            ((float4*)op)[d4] = v4;
        }
    }
}

// ======================= depthwise 3x3 conv on v, added into g_attn =======================
__global__ void dwc_add(const float* __restrict__ w, const float* __restrict__ bias)
{
    int n = blockIdx.x, b = blockIdx.y;
    int c = threadIdx.x;              // 512
    int i = n / WW, j = n % WW;
    float acc = bias[c];
#pragma unroll
    for (int di = 0; di < 3; di++) {
        int ii = i + di - 1;
        if (ii < 0 || ii > HH - 1) continue;
#pragma unroll
        for (int dj = 0; dj < 3; dj++) {
            int jj = j + dj - 1;
            if (jj < 0 || jj > WW - 1) continue;
            acc = fmaf(w[c * 9 + di * 3 + dj],
                       g_kv[((size_t)(b * NTOK + ii * WW + jj)) * (2 * DIM) + DIM + c], acc);
        }
    }
    g_attn[((size_t)(b * NTOK + n)) * DIM + c] += acc;
}

// ======================= launch =======================
extern "C" void kernel_launch(void* const* d_in, const int* in_sizes, int n_in,
                              void* d_out, int out_size)
{
    const float* x       = (const float*)d_in[0];
    const float* q_w     = (const float*)d_in[1];
    const float* kv_w    = (const float*)d_in[2];
    const float* proj_w  = (const float*)d_in[3];
    const float* proj_b  = (const float*)d_in[4];
    const float* dwc_w   = (const float*)d_in[5];
    const float* dwc_b   = (const float*)d_in[6];
    const float* an_bias = (const float*)d_in[7];
    const float* na_bias = (const float*)d_in[8];
    const float* ah_bias = (const float*)d_in[9];
    const float* aw_bias = (const float*)d_in[10];
    const float* ha_bias = (const float*)d_in[11];
    const float* wa_bias = (const float*)d_in[12];
    float* out = (float*)d_out;

    gemm_q <<<dim3(DIM / 128, (BATCH * NTOK) / 128), 256>>>(x, q_w);
    gemm_kv<<<dim3((2 * DIM) / 128, (BATCH * NTOK) / 128), 256>>>(x, kv_w);
    pool_agent<<<BATCH * DA, DIM>>>();
    build_bias<<<NH * DA, NTOK>>>(an_bias, na_bias, ah_bias, aw_bias, ha_bias, wa_bias);
    agent_attn<<<dim3(DA, NH, BATCH), 256>>>();
    q_attn<<<dim3(NH, BATCH), 256>>>();
    dwc_add<<<dim3(NTOK, BATCH), DIM>>>(dwc_w, dwc_b);
    gemm_proj<<<dim3(DIM / 128, (BATCH * NTOK) / 128), 256>>>(proj_w, proj_b, out);
}